// round 11
// baseline (speedup 1.0000x reference)
#include <cuda_runtime.h>
#include <cuda_bf16.h>
#include <cstdint>

// x: (128, 512, 14, 14) fp32 ; W: (20, 512) fp32
// T=8, n=16, B=3136, c=512, H=4, K=5, O=20
#define NT   128
#define CCH  512
#define HWS  196
#define TT   8
#define NN   16
#define HH   4
#define KK   5
#define OO   20
#define BB   3136   // NN * HWS

// scratch: softmax weights, layout [h][t][k][B]  (coalesced at both ends)
__device__ float g_weights[(size_t)HH * TT * KK * BB];
#define GW_IDX(h, t, k, b) ((((size_t)(h) * TT + (t)) * KK + (k)) * BB + (b))

// ---------------- kernel 1: TF32 MMA, direct-LDG A operands -----------------
// Rows flattened: r = nt*196 + sp in [0, 25088) -> 1568 m16 tiles exactly.
// grid = 392 CTAs x 128 threads (4 warps); warp w owns tile blockIdx.x*4+w.
// A-frags loaded directly from gmem (front-batched 32 LDG), B-frags from a
// compact conflict-free smem copy of W^T. No cp.async, no mainloop barriers.
#define KPITCH  24                    // Wt pitch: [512][24], conflict-free
#define DPITCH  25                    // Dx pitch: [64][25], conflict-free read
#define SMEM1_BYTES (CCH * KPITCH * 4)   // 49152

#define MMA_TF32(d, a0, a1, a2, a3, b0, b1)                                   \
    asm volatile("mma.sync.aligned.m16n8k8.row.col.f32.tf32.tf32.f32 "        \
                 "{%0,%1,%2,%3}, {%4,%5,%6,%7}, {%8,%9}, {%0,%1,%2,%3};"      \
                 : "+f"(d[0]), "+f"(d[1]), "+f"(d[2]), "+f"(d[3])             \
                 : "r"(a0), "r"(a1), "r"(a2), "r"(a3), "r"(b0), "r"(b1))

__global__ void __launch_bounds__(128)
weights_mma_kernel(const float* __restrict__ x, const float* __restrict__ W)
{
    extern __shared__ float smem[];
    float* Wt = smem;                      // [512][24] : Wt[k*24+n] = W[n][k]

    const int tid = threadIdx.x;
    const int w   = tid >> 5;
    const int l   = tid & 31;
    const int lg  = l >> 2;                // 0..7  (row group / n)
    const int lc  = l & 3;                 // 0..3  (k group)

    // stage W transposed (raw fp32; mma HW truncates to tf32)
    for (int i = tid; i < OO * CCH; i += 128) {
        const int n = i >> 9, k = i & (CCH - 1);
        Wt[k * KPITCH + n] = W[i];
    }
    __syncthreads();

    // this warp's two A-rows (flattened); tiles may span image boundaries
    const int j  = blockIdx.x * 4 + w;     // tile 0..1567
    const int r0 = 16 * j + lg;
    const int r1 = r0 + 8;
    const int nt0 = r0 / HWS, sp0 = r0 - nt0 * HWS;
    const int nt1 = r1 / HWS, sp1 = r1 - nt1 * HWS;
    const float* pa = x + (size_t)nt0 * CCH * HWS + (size_t)lc * HWS + sp0;
    const float* pb = x + (size_t)nt1 * CCH * HWS + (size_t)lc * HWS + sp1;

    float d[3][4];
#pragma unroll
    for (int nf = 0; nf < 3; ++nf)
#pragma unroll
        for (int r = 0; r < 4; ++r) d[nf][r] = 0.f;

    // 64 k-steps of 8 channels; front-batch 8 k-steps (32 outstanding LDG)
    for (int ks0 = 0; ks0 < 64; ks0 += 8) {
        float a0[8], a1[8], a2[8], a3[8];
#pragma unroll
        for (int jj = 0; jj < 8; ++jj) {
            const size_t o = (size_t)(ks0 + jj) * 8 * HWS;
            a0[jj] = pa[o];
            a1[jj] = pb[o];
            a2[jj] = pa[o + 4 * HWS];
            a3[jj] = pb[o + 4 * HWS];
        }
#pragma unroll
        for (int jj = 0; jj < 8; ++jj) {
            const int kg = (ks0 + jj) * 8 + lc;
            const float* w0 = Wt + kg * KPITCH + lg;
            const float* w1 = Wt + (kg + 4) * KPITCH + lg;
#pragma unroll
            for (int nf = 0; nf < 3; ++nf) {
                const uint32_t b0 = __float_as_uint(w0[8 * nf]);
                const uint32_t b1 = __float_as_uint(w1[8 * nf]);
                MMA_TF32(d[nf],
                         __float_as_uint(a0[jj]), __float_as_uint(a1[jj]),
                         __float_as_uint(a2[jj]), __float_as_uint(a3[jj]),
                         b0, b1);
            }
        }
    }

    // exchange D through smem (overwrite Wt): Dx[64][25]
    __syncthreads();
    float* Dx = smem;
    {
        const int lr = 16 * w + lg;        // local row 0..63
#pragma unroll
        for (int nf = 0; nf < 3; ++nf) {
            const int col = nf * 8 + 2 * lc;
            Dx[lr * DPITCH + col]           = d[nf][0];
            Dx[lr * DPITCH + col + 1]       = d[nf][1];
            Dx[(lr + 8) * DPITCH + col]     = d[nf][2];
            Dx[(lr + 8) * DPITCH + col + 1] = d[nf][3];
        }
    }
    __syncthreads();

    // softmax per row; stores coalesced-ish in [h][t][k][B] layout
    if (tid < 64) {
        const int r   = blockIdx.x * 64 + tid;
        const int nt  = r / HWS;
        const int sp  = r - nt * HWS;
        const int t_  = nt & (TT - 1);
        const int b   = (nt >> 3) * HWS + sp;
        const float* row = Dx + tid * DPITCH;
#pragma unroll
        for (int h = 0; h < HH; ++h) {
            float lo[KK];
#pragma unroll
            for (int k = 0; k < KK; ++k) lo[k] = row[h * KK + k];
            float m = lo[0];
#pragma unroll
            for (int k = 1; k < KK; ++k) m = fmaxf(m, lo[k]);
            float e[KK], sum = 0.f;
#pragma unroll
            for (int k = 0; k < KK; ++k) { e[k] = __expf(lo[k] - m); sum += e[k]; }
            const float inv = 1.f / sum;
#pragma unroll
            for (int k = 0; k < KK; ++k)
                g_weights[GW_IDX(h, t_, k, b)] = e[k] * inv;
        }
    }
}

// ---------------- kernel 2: causal 5-tap combine (R9 exact) -----------------
// grid = (n_i : 16, ct : 64) ; block = 224 threads (196 active = spatial pos).
// Weights read coalesced: 40 independent LDG.32 per thread (L2-resident),
// held in registers.
__global__ void __launch_bounds__(224)
combine_kernel(const float* __restrict__ x, float* __restrict__ out)
{
    const int n_i = blockIdx.x;
    const int ct  = blockIdx.y;           // channel tile of 8
    const int h   = ct >> 4;

    const int sp = threadIdx.x;
    if (sp >= HWS) return;

    const int b = n_i * HWS + sp;
    float wt[TT * KK];
#pragma unroll
    for (int t = 0; t < TT; ++t)
#pragma unroll
        for (int k = 0; k < KK; ++k)
            wt[t * KK + k] = g_weights[GW_IDX(h, t, k, b)];

    const size_t tstride = (size_t)CCH * HWS;
    const size_t base = ((size_t)n_i * TT * CCH + (size_t)ct * 8) * HWS + sp;

#pragma unroll
    for (int cp = 0; cp < 4; ++cp) {
        const float* xp0 = x + base + (size_t)(2 * cp) * HWS;
        const float* xp1 = xp0 + HWS;
        float a[TT], bv[TT];
#pragma unroll
        for (int t = 0; t < TT; ++t) a[t]  = xp0[(size_t)t * tstride];
#pragma unroll
        for (int t = 0; t < TT; ++t) bv[t] = xp1[(size_t)t * tstride];

        float* op0 = out + base + (size_t)(2 * cp) * HWS;
        float* op1 = op0 + HWS;
#pragma unroll
        for (int t = 0; t < TT; ++t) {
            float s0 = 0.f, s1 = 0.f;
#pragma unroll
            for (int k = 0; k < KK; ++k) {
                const int src = t + k - 4;
                if (src >= 0) {
                    s0 = fmaf(wt[t * KK + k], a[src],  s0);
                    s1 = fmaf(wt[t * KK + k], bv[src], s1);
                }
            }
            op0[(size_t)t * tstride] = s0;
            op1[(size_t)t * tstride] = s1;
        }
    }
}

// ---------------------------------------------------------------------------
extern "C" void kernel_launch(void* const* d_in, const int* in_sizes, int n_in,
                              void* d_out, int out_size)
{
    const float* x = (const float*)d_in[0];
    const float* W = (const float*)d_in[1];
    float* out = (float*)d_out;

    cudaFuncSetAttribute(weights_mma_kernel,
                         cudaFuncAttributeMaxDynamicSharedMemorySize, SMEM1_BYTES);

    weights_mma_kernel<<<392, 128, SMEM1_BYTES>>>(x, W);
    combine_kernel<<<dim3(NN, 64), 224>>>(x, out);
}

// round 13
// speedup vs baseline: 1.6545x; 1.6545x over previous
#include <cuda_runtime.h>
#include <cuda_bf16.h>
#include <cstdint>

// x: (128, 512, 14, 14) fp32 ; W: (20, 512) fp32
// T=8, n=16, B=3136, c=512, H=4, K=5, O=20
#define NT   128
#define CCH  512
#define HWS  196
#define TT   8
#define NN   16
#define HH   4
#define KK   5
#define OO   20
#define BB   3136   // NN * HWS

// scratch: softmax weights, layout [h][t][k][B]  (coalesced at both ends)
__device__ float g_weights[(size_t)HH * TT * KK * BB];
#define GW_IDX(h, t, k, b) ((((size_t)(h) * TT + (t)) * KK + (k)) * BB + (b))

// ---------------- kernel 1: TF32 tensor-core logits + softmax ----------------
// grid = 256: blockIdx.x = nt*2 + half. half0 -> sp [0,96), half1 -> sp [96,196).
// 256 threads (8 warps). Double-buffered cp.async, 32-channel chunks.
// smem = 2 A-buffers (26.6KB) + W^T (40KB) + 64B guard = 67.6KB -> 3 CTAs/SM
// -> ALL 256 CTAs resident in one wave (cross-CTA latency overlap).
#define KC      32                    // channels per staged chunk
#define NCHUNK  16                    // 512 / 32
#define NBUF    2
#define APITCH  104                   // smem pitch (104%32==8 -> conflict-free)
#define ABUF    (KC * APITCH)         // 3328 floats per buffer
#define WTP     20                    // W^T pitch: Wt[k][n], n=0..19
// +16 floats guard: b-frag lanes with n=20..23 read up to Wt[511*20+23],
// 12B past the tight end (values are garbage, discarded; address must be legal)
#define SMEM1_BYTES ((NBUF * ABUF + CCH * WTP + 16) * 4)   // 67648

__device__ __forceinline__ uint32_t smem_u32(const void* p) {
    uint32_t a;
    asm("{ .reg .u64 t; cvta.to.shared.u64 t, %1; cvt.u32.u64 %0, t; }"
        : "=r"(a) : "l"(p));
    return a;
}

#define MMA_TF32(d, a0, a1, a2, a3, b0, b1)                                   \
    asm volatile("mma.sync.aligned.m16n8k8.row.col.f32.tf32.tf32.f32 "        \
                 "{%0,%1,%2,%3}, {%4,%5,%6,%7}, {%8,%9}, {%0,%1,%2,%3};"      \
                 : "+f"(d[0]), "+f"(d[1]), "+f"(d[2]), "+f"(d[3])             \
                 : "r"(a0), "r"(a1), "r"(a2), "r"(a3), "r"(b0), "r"(b1))

#define CP16(daddr, saddr)                                                    \
    asm volatile("cp.async.cg.shared.global [%0], [%1], 16;"                  \
                 :: "r"(daddr), "l"((const void*)(saddr)) : "memory")

__global__ void __launch_bounds__(256)
weights_mma_kernel(const float* __restrict__ x, const float* __restrict__ W)
{
    extern __shared__ float smem[];
    float* Abuf = smem;                    // [2][KC][APITCH]
    float* Wt   = smem + NBUF * ABUF;      // [512][20] : Wt[k*20+n] = W[n][k]

    const int tid  = threadIdx.x;
    const int bid  = blockIdx.x;
    const int nt   = bid >> 1;             // image 0..127
    const int half = bid & 1;
    const int off  = half * 96;            // global sp offset of this half
    const int nsp  = half ? 100 : 96;
    const int ntiles = half ? 7 : 6;       // m16 tiles

    const int w  = tid >> 5;
    const int l  = tid & 31;
    const int lg = l >> 2;                 // 0..7
    const int lc = l & 3;                  // 0..3

    // stage W transposed (raw fp32; mma HW truncates to tf32)
    for (int i = tid; i < OO * CCH; i += 256) {
        const int n = i >> 9, k = i & (CCH - 1);
        Wt[k * WTP + n] = W[i];
    }

    const float* xbase = x + (size_t)nt * CCH * HWS + off;
    const uint32_t abase_u32 = smem_u32(Abuf);

    // staging: compile-time divisor per half (no runtime IDIV)
    auto stage = [&](int ck) {
        const float* src = xbase + (size_t)ck * KC * HWS;
        const uint32_t dst0 = abase_u32 + (ck & (NBUF - 1)) * (ABUF * 4);
        if (half == 0) {
            for (int f = tid; f < KC * 24; f += 256) {
                const int c = f / 24, i = f - c * 24;
                CP16(dst0 + (c * APITCH + 4 * i) * 4, src + c * HWS + 4 * i);
            }
        } else {
            for (int f = tid; f < KC * 25; f += 256) {
                const int c = f / 25, i = f - c * 25;
                CP16(dst0 + (c * APITCH + 4 * i) * 4, src + c * HWS + 4 * i);
            }
        }
        asm volatile("cp.async.commit_group;" ::: "memory");
    };

    // one m16 tile per warp
    const bool tvalid = (w < ntiles);
    const int sp0 = 16 * w + lg;
    const int spa = min(sp0, APITCH - 1);       // clamped rows never stored
    const int spb = min(sp0 + 8, APITCH - 1);

    float d[3][4];
#pragma unroll
    for (int nf = 0; nf < 3; ++nf)
#pragma unroll
        for (int r = 0; r < 4; ++r) d[nf][r] = 0.f;

    stage(0); stage(1);                    // both buffers in flight

    for (int ck = 0; ck < NCHUNK; ++ck) {
        // exact wait: staged_through = min(ck+1, NCHUNK-1); pending = that - ck
        if (ck < NCHUNK - 1) {
            asm volatile("cp.async.wait_group 1;" ::: "memory");
        } else {
            asm volatile("cp.async.wait_group 0;" ::: "memory");
        }
        __syncthreads();                   // chunk ck visible to all (incl Wt ck=0)

        const float* Ab = Abuf + (ck & (NBUF - 1)) * ABUF;
#pragma unroll
        for (int k8 = 0; k8 < KC / 8; ++k8) {
            const int kl = k8 * 8;
            const int kg = ck * KC + kl + lc;
            uint32_t bfr[3][2];
#pragma unroll
            for (int nf = 0; nf < 3; ++nf) {
                bfr[nf][0] = __float_as_uint(Wt[kg * WTP + 8 * nf + lg]);
                bfr[nf][1] = __float_as_uint(Wt[(kg + 4) * WTP + 8 * nf + lg]);
            }
            if (tvalid) {
                const float* r0 = Ab + (kl + lc) * APITCH;
                const float* r4 = Ab + (kl + lc + 4) * APITCH;
                const uint32_t a0 = __float_as_uint(r0[spa]);
                const uint32_t a1 = __float_as_uint(r0[spb]);
                const uint32_t a2 = __float_as_uint(r4[spa]);
                const uint32_t a3 = __float_as_uint(r4[spb]);
#pragma unroll
                for (int nf = 0; nf < 3; ++nf)
                    MMA_TF32(d[nf], a0, a1, a2, a3, bfr[nf][0], bfr[nf][1]);
            }
        }
        __syncthreads();                   // buf consumed, safe to restage
        if (ck + 2 < NCHUNK) stage(ck + 2);
    }

    // exchange D through smem (reuse Abuf region): Dx[112][24]
    float* Dx = smem;
    if (tvalid) {
        const int r = 16 * w + lg;
#pragma unroll
        for (int nf = 0; nf < 3; ++nf) {
            const int col = nf * 8 + 2 * lc;
            Dx[r * 24 + col]           = d[nf][0];
            Dx[r * 24 + col + 1]       = d[nf][1];
            Dx[(r + 8) * 24 + col]     = d[nf][2];
            Dx[(r + 8) * 24 + col + 1] = d[nf][3];
        }
    }
    __syncthreads();

    // per-position softmax; stores coalesced in [h][t][k][B] layout
    const int t_  = nt & (TT - 1);
    const int n_i = nt >> 3;
    for (int s = tid; s < nsp; s += 256) {
        const float* row = Dx + s * 24;
        const int b = n_i * HWS + off + s;
#pragma unroll
        for (int h = 0; h < HH; ++h) {
            float lo[KK];
#pragma unroll
            for (int k = 0; k < KK; ++k) lo[k] = row[h * KK + k];
            float m = lo[0];
#pragma unroll
            for (int k = 1; k < KK; ++k) m = fmaxf(m, lo[k]);
            float e[KK], sum = 0.f;
#pragma unroll
            for (int k = 0; k < KK; ++k) { e[k] = __expf(lo[k] - m); sum += e[k]; }
            const float inv = 1.f / sum;
#pragma unroll
            for (int k = 0; k < KK; ++k)
                g_weights[GW_IDX(h, t_, k, b)] = e[k] * inv;
        }
    }
}

// ---------------- kernel 2: causal 5-tap combine (R11 exact) ----------------
// grid = (n_i : 16, ct : 64) ; block = 224 threads (196 active = spatial pos).
// Weights read coalesced: 40 independent LDG.32 per thread (L2-resident),
// held in registers.
__global__ void __launch_bounds__(224)
combine_kernel(const float* __restrict__ x, float* __restrict__ out)
{
    const int n_i = blockIdx.x;
    const int ct  = blockIdx.y;           // channel tile of 8
    const int h   = ct >> 4;

    const int sp = threadIdx.x;
    if (sp >= HWS) return;

    const int b = n_i * HWS + sp;
    float wt[TT * KK];
#pragma unroll
    for (int t = 0; t < TT; ++t)
#pragma unroll
        for (int k = 0; k < KK; ++k)
            wt[t * KK + k] = g_weights[GW_IDX(h, t, k, b)];

    const size_t tstride = (size_t)CCH * HWS;
    const size_t base = ((size_t)n_i * TT * CCH + (size_t)ct * 8) * HWS + sp;

#pragma unroll
    for (int cp = 0; cp < 4; ++cp) {
        const float* xp0 = x + base + (size_t)(2 * cp) * HWS;
        const float* xp1 = xp0 + HWS;
        float a[TT], bv[TT];
#pragma unroll
        for (int t = 0; t < TT; ++t) a[t]  = xp0[(size_t)t * tstride];
#pragma unroll
        for (int t = 0; t < TT; ++t) bv[t] = xp1[(size_t)t * tstride];

        float* op0 = out + base + (size_t)(2 * cp) * HWS;
        float* op1 = op0 + HWS;
#pragma unroll
        for (int t = 0; t < TT; ++t) {
            float s0 = 0.f, s1 = 0.f;
#pragma unroll
            for (int k = 0; k < KK; ++k) {
                const int src = t + k - 4;
                if (src >= 0) {
                    s0 = fmaf(wt[t * KK + k], a[src],  s0);
                    s1 = fmaf(wt[t * KK + k], bv[src], s1);
                }
            }
            op0[(size_t)t * tstride] = s0;
            op1[(size_t)t * tstride] = s1;
        }
    }
}

// ---------------------------------------------------------------------------
extern "C" void kernel_launch(void* const* d_in, const int* in_sizes, int n_in,
                              void* d_out, int out_size)
{
    const float* x = (const float*)d_in[0];
    const float* W = (const float*)d_in[1];
    float* out = (float*)d_out;

    cudaFuncSetAttribute(weights_mma_kernel,
                         cudaFuncAttributeMaxDynamicSharedMemorySize, SMEM1_BYTES);

    weights_mma_kernel<<<2 * NT, 256, SMEM1_BYTES>>>(x, W);
    combine_kernel<<<dim3(NN, 64), 224>>>(x, out);
}